// round 14
// baseline (speedup 1.0000x reference)
#include <cuda_runtime.h>
#include <cuda_bf16.h>
#include <cuda_fp16.h>
#include <cstdint>

// Problem constants (fixed by the reference)
#define N_NODES 50000
#define N_EDGES 800000
#define NFEAT   512
#define NHID    128
#define NCLASS  40

#define EC      16                 // edges per chunk (800000 % 16 == 0)
#define N_CHUNK (N_EDGES / EC)     // 50000

// Device scratch (no cudaMalloc allowed)
__device__ __half g_h1h[N_NODES * NHID];  // support1 = x @ W1 (fp16, 12.8 MB)
__device__ float g_agg1[N_NODES * NHID];  // aggregated layer-1 out
__device__ float g_h2[N_NODES * NCLASS];  // support2 = relu(h) @ W2

// sort scratch (g_count is zero at module load; scatter re-zeroes it each call)
__device__ int   g_count[N_NODES];
__device__ int   g_rank[N_EDGES];
__device__ int   g_off[N_NODES];
#define N_BLK ((N_NODES + 255) / 256)     // 196
__device__ int   g_bsum[N_BLK];
__device__ int4  g_edge_s[N_EDGES];       // (src, w_bits, dst, 0) sorted by dst

__device__ __forceinline__ uint32_t cvt_tf32(float f) {
    uint32_t out;
    asm("cvt.rna.tf32.f32 %0, %1;" : "=r"(out) : "f"(f));
    return out;
}

__device__ __forceinline__ void mma_tf32(
    float& d0, float& d1, float& d2, float& d3,
    uint32_t a0, uint32_t a1, uint32_t a2, uint32_t a3,
    uint32_t b0, uint32_t b1)
{
    asm volatile(
        "mma.sync.aligned.m16n8k8.row.col.f32.tf32.tf32.f32 "
        "{%0,%1,%2,%3}, {%4,%5,%6,%7}, {%8,%9}, {%0,%1,%2,%3};"
        : "+f"(d0), "+f"(d1), "+f"(d2), "+f"(d3)
        : "r"(a0), "r"(a1), "r"(a2), "r"(a3), "r"(b0), "r"(b1));
}

__device__ __forceinline__ void red_add_v4(float* addr, float4 v)
{
    asm volatile("red.global.add.v4.f32 [%0], {%1, %2, %3, %4};"
                 :: "l"(addr), "f"(v.x), "f"(v.y), "f"(v.z), "f"(v.w)
                 : "memory");
}

// ===========================================================================
// GEMM1 (HMMA tf32): h1h[M,128] = tf32(A[M,512]) @ tf32(W1[512,128]) -> fp16
// CTA tile 128x128, BK=32, 8 warps, warp tile 32(M) x 64(N).
// Register-preload pipeline: tile k+1 LDGs issue before compute of tile k.
// ===========================================================================
#define G1_BK 32

__global__ __launch_bounds__(256) void gemm1_mma_kernel(
    const float* __restrict__ A, const float* __restrict__ W1, int M)
{
    __shared__ uint32_t sA[4 * 8 * 32 * 4];   // 16 KB
    __shared__ uint32_t sB[4 * 8 * 32 * 4];   // 16 KB

    const int tid  = threadIdx.x;
    const int lane = tid & 31;
    const int wid  = tid >> 5;
    const int warp_m = wid & 3;
    const int warp_n = wid >> 2;
    const int m0 = blockIdx.x * 128;

    float acc[2][8][4];
#pragma unroll
    for (int mi = 0; mi < 2; mi++)
#pragma unroll
        for (int nt = 0; nt < 8; nt++)
#pragma unroll
            for (int j = 0; j < 4; j++) acc[mi][nt][j] = 0.0f;

    // per-thread gmem coordinates (loop-invariant)
    float4 pa[4], pb[4];
    int a_row[4], a_q[4], b_kk[4], b_nf[4];
#pragma unroll
    for (int t = 0; t < 4; t++) {
        int i = tid + t * 256;
        a_row[t] = i >> 3;  a_q[t] = i & 7;
        b_kk[t]  = i >> 5;  b_nf[t] = i & 31;
    }

    auto load_tiles = [&](int k0) {
#pragma unroll
        for (int t = 0; t < 4; t++) {
            pa[t] = make_float4(0.f, 0.f, 0.f, 0.f);
            if (m0 + a_row[t] < M)
                pa[t] = *(const float4*)&A[(size_t)(m0 + a_row[t]) * NFEAT + k0 + a_q[t] * 4];
            pb[t] = *(const float4*)&W1[(size_t)(k0 + b_kk[t]) * NHID + b_nf[t] * 4];
        }
    };

    load_tiles(0);

    for (int kc = 0; kc < NFEAT / G1_BK; kc++) {
        // ---- stage regs -> smem (frag-permuted, with cvt) ----
#pragma unroll
        for (int t = 0; t < 4; t++) {
            int r = a_row[t], q = a_q[t];
            uint32_t u[4] = {cvt_tf32(pa[t].x), cvt_tf32(pa[t].y),
                             cvt_tf32(pa[t].z), cvt_tf32(pa[t].w)};
            int ks   = q >> 1;
            int mt   = r >> 4;
            int slot = ((r >> 3) & 1) + 2 * (q & 1);
            int base = ((ks * 8 + mt) * 32 + (r & 7) * 4) * 4 + slot;
#pragma unroll
            for (int j = 0; j < 4; j++) sA[base + j * 4] = u[j];
        }
#pragma unroll
        for (int t = 0; t < 4; t++) {
            int kk = b_kk[t], nf = b_nf[t];
            uint32_t u[4] = {cvt_tf32(pb[t].x), cvt_tf32(pb[t].y),
                             cvt_tf32(pb[t].z), cvt_tf32(pb[t].w)};
            int ks   = kk >> 3;
            int kc2  = kk & 7;
            int ntp  = nf >> 2;
            int slot = ((nf >> 1) & 1) * 2 + (kc2 >> 2);
            int base = ((ks * 8 + ntp) * 32 + (nf & 1) * 16 + (kc2 & 3)) * 4 + slot;
#pragma unroll
            for (int j = 0; j < 4; j++) sB[base + j * 16] = u[j];
        }
        __syncthreads();

        // ---- preload next tile (overlaps with compute below) ----
        if (kc + 1 < NFEAT / G1_BK) load_tiles((kc + 1) * G1_BK);

        // ---- compute: 4 k-steps of K=8 ----
#pragma unroll
        for (int ks = 0; ks < 4; ks++) {
            uint4 af[2];
#pragma unroll
            for (int mi = 0; mi < 2; mi++) {
                int mt = warp_m * 2 + mi;
                af[mi] = *(const uint4*)&sA[((ks * 8 + mt) * 32 + lane) * 4];
            }
#pragma unroll
            for (int np = 0; np < 4; np++) {
                int ntp = warp_n * 4 + np;
                uint4 bf = *(const uint4*)&sB[((ks * 8 + ntp) * 32 + lane) * 4];
#pragma unroll
                for (int mi = 0; mi < 2; mi++) {
                    mma_tf32(acc[mi][np*2][0], acc[mi][np*2][1],
                             acc[mi][np*2][2], acc[mi][np*2][3],
                             af[mi].x, af[mi].y, af[mi].z, af[mi].w,
                             bf.x, bf.y);
                    mma_tf32(acc[mi][np*2+1][0], acc[mi][np*2+1][1],
                             acc[mi][np*2+1][2], acc[mi][np*2+1][3],
                             af[mi].x, af[mi].y, af[mi].z, af[mi].w,
                             bf.z, bf.w);
                }
            }
        }
        __syncthreads();
    }

    // epilogue -> fp16 h1
#pragma unroll
    for (int mi = 0; mi < 2; mi++) {
        int r_base = m0 + warp_m * 32 + mi * 16 + (lane >> 2);
#pragma unroll
        for (int nt = 0; nt < 8; nt++) {
            int col = warp_n * 64 + nt * 8 + (lane & 3) * 2;
            if (r_base < M)
                *(__half2*)&g_h1h[(size_t)r_base * NHID + col] =
                    __floats2half2_rn(acc[mi][nt][0], acc[mi][nt][1]);
            if (r_base + 8 < M)
                *(__half2*)&g_h1h[(size_t)(r_base + 8) * NHID + col] =
                    __floats2half2_rn(acc[mi][nt][2], acc[mi][nt][3]);
        }
    }
}

// ===========================================================================
// Sort build: hist(+rank) -> blocksum -> offsets(incl. bsum scan) -> scatter
// (scatter re-zeroes g_count for the next launch/replay)
// ===========================================================================
__global__ void hist_kernel(const int* __restrict__ edst)
{
    int e = blockIdx.x * blockDim.x + threadIdx.x;
    if (e < N_EDGES) g_rank[e] = atomicAdd(&g_count[edst[e]], 1);
}

__global__ __launch_bounds__(256) void blocksum_kernel()
{
    __shared__ int ws[8];
    int i = blockIdx.x * 256 + threadIdx.x;
    int c = (i < N_NODES) ? g_count[i] : 0;
    int lane = threadIdx.x & 31, w = threadIdx.x >> 5;
    int v = c;
#pragma unroll
    for (int o = 16; o > 0; o >>= 1) v += __shfl_down_sync(0xFFFFFFFFu, v, o);
    if (lane == 0) ws[w] = v;
    __syncthreads();
    if (threadIdx.x == 0) {
        int s = 0;
#pragma unroll
        for (int j = 0; j < 8; j++) s += ws[j];
        g_bsum[blockIdx.x] = s;
    }
}

// every block redundantly scans the 196 block sums, then scans its 256 counts
__global__ __launch_bounds__(256) void offsets_kernel()
{
    __shared__ int sb[256];
    __shared__ int sm[256];
    const int tid = threadIdx.x;

    int bsv = (tid < N_BLK) ? g_bsum[tid] : 0;
    sb[tid] = bsv;
    __syncthreads();
#pragma unroll
    for (int o = 1; o < 256; o <<= 1) {
        int n = (tid >= o) ? sb[tid - o] : 0;
        __syncthreads();
        sb[tid] += n;
        __syncthreads();
    }
    int blk_excl = sb[blockIdx.x] - g_bsum[blockIdx.x];

    int i = blockIdx.x * 256 + tid;
    int c = (i < N_NODES) ? g_count[i] : 0;
    sm[tid] = c;
    __syncthreads();
#pragma unroll
    for (int o = 1; o < 256; o <<= 1) {
        int n = (tid >= o) ? sm[tid - o] : 0;
        __syncthreads();
        sm[tid] += n;
        __syncthreads();
    }
    if (i < N_NODES) g_off[i] = blk_excl + sm[tid] - c;
}

__global__ void scatter_kernel(const int* __restrict__ esrc,
                               const int* __restrict__ edst,
                               const float* __restrict__ ew)
{
    int e = blockIdx.x * blockDim.x + threadIdx.x;
    if (e >= N_EDGES) return;
    int d = edst[e];
    int pos = g_off[d] + g_rank[e];
    g_edge_s[pos] = make_int4(esrc[e], __float_as_int(ew[e]), d, 0);
    if (e < N_NODES) g_count[e] = 0;   // ready for next launch (g_off already built)
}

// ---------------------------------------------------------------------------
// Bias-broadcast initializers (reductions land on top)
// ---------------------------------------------------------------------------
__global__ void init_bias128_kernel(float* __restrict__ dst,
                                    const float* __restrict__ b)
{
    __shared__ float sb[NHID];
    if (threadIdx.x < NHID) sb[threadIdx.x] = b[threadIdx.x];
    __syncthreads();
    size_t idx = (size_t)blockIdx.x * blockDim.x + threadIdx.x;
    size_t total = (size_t)N_NODES * NHID;
    if (idx < total) dst[idx] = sb[idx & (NHID - 1)];
}

__global__ void init_bias40_kernel(float* __restrict__ dst,
                                   const float* __restrict__ b)
{
    __shared__ float sb[NCLASS];
    if (threadIdx.x < NCLASS) sb[threadIdx.x] = b[threadIdx.x];
    __syncthreads();
    size_t idx = (size_t)blockIdx.x * blockDim.x + threadIdx.x;
    size_t total = (size_t)N_NODES * NCLASS;
    if (idx < total) dst[idx] = sb[idx % NCLASS];
}

// ===========================================================================
// SpMM layer 1: warp per 16-edge chunk, two-phase halves of 8.
// Phase 1: batch-load 8 edge records + 8 weighted gathers (MLP=8, no barriers)
// Phase 2: run-detect + RED at boundaries only.
// ===========================================================================
__global__ __launch_bounds__(256) void spmm1_seg_kernel()
{
    const int wid  = threadIdx.x >> 5;
    const int lane = threadIdx.x & 31;
    const int chunk = blockIdx.x * 8 + wid;
    if (chunk >= N_CHUNK) return;
    const int base = chunk * EC;

    float4 acc = make_float4(0.f, 0.f, 0.f, 0.f);
    int cur_d = g_edge_s[base].z;

#pragma unroll
    for (int h = 0; h < 2; h++) {
        int4  ed[8];
        float4 val[8];
        // phase 1: all loads, no compiler barriers in between
#pragma unroll
        for (int i = 0; i < 8; i++)
            ed[i] = g_edge_s[base + h * 8 + i];
#pragma unroll
        for (int i = 0; i < 8; i++) {
            uint2 raw = *(const uint2*)&g_h1h[(size_t)ed[i].x * NHID + lane * 4];
            float w = __int_as_float(ed[i].y);
            float2 f0 = __half22float2(*(__half2*)&raw.x);
            float2 f1 = __half22float2(*(__half2*)&raw.y);
            val[i] = make_float4(w * f0.x, w * f0.y, w * f1.x, w * f1.y);
        }
        // phase 2: merge
#pragma unroll
        for (int i = 0; i < 8; i++) {
            if (ed[i].z != cur_d) {     // warp-uniform branch
                red_add_v4(&g_agg1[(size_t)cur_d * NHID + lane * 4], acc);
                acc = make_float4(0.f, 0.f, 0.f, 0.f);
                cur_d = ed[i].z;
            }
            acc.x += val[i].x; acc.y += val[i].y;
            acc.z += val[i].z; acc.w += val[i].w;
        }
    }
    red_add_v4(&g_agg1[(size_t)cur_d * NHID + lane * 4], acc);
}

// ===========================================================================
// GEMM2 (HMMA tf32): C[M,40] = tf32(relu(H[M,128])) @ tf32(W2[128,40])
// ===========================================================================
__global__ __launch_bounds__(256) void gemm2_mma_kernel(
    const float* __restrict__ H, const float* __restrict__ W2,
    float* __restrict__ C, int M)
{
    __shared__ uint32_t sH[4 * 8 * 32 * 4];    // 16 KB
    __shared__ uint32_t sW2[16 * 3 * 32 * 4];  // 24 KB

    const int tid  = threadIdx.x;
    const int lane = tid & 31;
    const int wid  = tid >> 5;
    const int m0 = blockIdx.x * 128;

    for (int i = tid; i < 1280; i += 256) {
        int kk = i / 10;
        int nf = i % 10;
        float4 v = *(const float4*)&W2[(size_t)kk * NCLASS + nf * 4];
        uint32_t u[4] = {cvt_tf32(v.x), cvt_tf32(v.y), cvt_tf32(v.z), cvt_tf32(v.w)};
        int gks  = kk >> 3;
        int kc   = kk & 7;
        int ntp  = nf >> 2;
        int slot = ((nf >> 1) & 1) * 2 + (kc >> 2);
        int base = ((gks * 3 + ntp) * 32 + (nf & 1) * 16 + (kc & 3)) * 4 + slot;
#pragma unroll
        for (int j = 0; j < 4; j++) sW2[base + j * 16] = u[j];
    }

    float acc[5][4];
#pragma unroll
    for (int nt = 0; nt < 5; nt++)
#pragma unroll
        for (int j = 0; j < 4; j++) acc[nt][j] = 0.0f;

    for (int kc4 = 0; kc4 < 4; kc4++) {
        __syncthreads();
#pragma unroll
        for (int t = 0; t < 4; t++) {
            int i = tid + t * 256;
            int r = i >> 3;
            int q = i & 7;
            float4 v = make_float4(0.f, 0.f, 0.f, 0.f);
            if (m0 + r < M) {
                v = *(const float4*)&H[(size_t)(m0 + r) * NHID + kc4 * 32 + q * 4];
                v.x = fmaxf(v.x, 0.f); v.y = fmaxf(v.y, 0.f);
                v.z = fmaxf(v.z, 0.f); v.w = fmaxf(v.w, 0.f);
            }
            uint32_t u[4] = {cvt_tf32(v.x), cvt_tf32(v.y), cvt_tf32(v.z), cvt_tf32(v.w)};
            int ks   = q >> 1;
            int mt   = r >> 4;
            int slot = ((r >> 3) & 1) + 2 * (q & 1);
            int base = ((ks * 8 + mt) * 32 + (r & 7) * 4) * 4 + slot;
#pragma unroll
            for (int j = 0; j < 4; j++) sH[base + j * 4] = u[j];
        }
        __syncthreads();

#pragma unroll
        for (int ks = 0; ks < 4; ks++) {
            int gks = kc4 * 4 + ks;
            uint4 af = *(const uint4*)&sH[((ks * 8 + wid) * 32 + lane) * 4];
            uint4 b0 = *(const uint4*)&sW2[((gks * 3 + 0) * 32 + lane) * 4];
            uint4 b1 = *(const uint4*)&sW2[((gks * 3 + 1) * 32 + lane) * 4];
            uint4 b2 = *(const uint4*)&sW2[((gks * 3 + 2) * 32 + lane) * 4];
            mma_tf32(acc[0][0], acc[0][1], acc[0][2], acc[0][3],
                     af.x, af.y, af.z, af.w, b0.x, b0.y);
            mma_tf32(acc[1][0], acc[1][1], acc[1][2], acc[1][3],
                     af.x, af.y, af.z, af.w, b0.z, b0.w);
            mma_tf32(acc[2][0], acc[2][1], acc[2][2], acc[2][3],
                     af.x, af.y, af.z, af.w, b1.x, b1.y);
            mma_tf32(acc[3][0], acc[3][1], acc[3][2], acc[3][3],
                     af.x, af.y, af.z, af.w, b1.z, b1.w);
            mma_tf32(acc[4][0], acc[4][1], acc[4][2], acc[4][3],
                     af.x, af.y, af.z, af.w, b2.x, b2.y);
        }
    }

    int r = m0 + wid * 16 + (lane >> 2);
#pragma unroll
    for (int nt = 0; nt < 5; nt++) {
        int col = nt * 8 + (lane & 3) * 2;
        if (r < M)
            *(float2*)&C[(size_t)r * NCLASS + col] =
                make_float2(acc[nt][0], acc[nt][1]);
        if (r + 8 < M)
            *(float2*)&C[(size_t)(r + 8) * NCLASS + col] =
                make_float2(acc[nt][2], acc[nt][3]);
    }
}

// ===========================================================================
// SpMM layer 2: thread = (16-edge chunk, float4-chunk c of 10), two-phase
// ===========================================================================
__global__ __launch_bounds__(256) void spmm2_seg_kernel(float* __restrict__ out)
{
    unsigned gid = blockIdx.x * blockDim.x + threadIdx.x;
    unsigned chunk = gid / 10;
    unsigned c = gid % 10;
    if (chunk >= N_CHUNK) return;
    const int base = chunk * EC;

    float4 acc = make_float4(0.f, 0.f, 0.f, 0.f);
    int cur_d = g_edge_s[base].z;

#pragma unroll
    for (int h = 0; h < 2; h++) {
        int4  ed[8];
        float4 val[8];
#pragma unroll
        for (int i = 0; i < 8; i++)
            ed[i] = g_edge_s[base + h * 8 + i];
#pragma unroll
        for (int i = 0; i < 8; i++) {
            float4 v = *(const float4*)&g_h2[(size_t)ed[i].x * NCLASS + c * 4];
            float w = __int_as_float(ed[i].y);
            val[i] = make_float4(w * v.x, w * v.y, w * v.z, w * v.w);
        }
#pragma unroll
        for (int i = 0; i < 8; i++) {
            if (ed[i].z != cur_d) {
                red_add_v4(&out[(size_t)cur_d * NCLASS + c * 4], acc);
                acc = make_float4(0.f, 0.f, 0.f, 0.f);
                cur_d = ed[i].z;
            }
            acc.x += val[i].x; acc.y += val[i].y;
            acc.z += val[i].z; acc.w += val[i].w;
        }
    }
    red_add_v4(&out[(size_t)cur_d * NCLASS + c * 4], acc);
}

// ---------------------------------------------------------------------------
// kernel_launch
// inputs: 0=x 1=edge_src 2=edge_dst 3=edge_weight 4=W1 5=b1 6=W2 7=b2
// ---------------------------------------------------------------------------
extern "C" void kernel_launch(void* const* d_in, const int* in_sizes, int n_in,
                              void* d_out, int out_size)
{
    const float* x   = (const float*)d_in[0];
    const int*   es  = (const int*)d_in[1];
    const int*   ed  = (const int*)d_in[2];
    const float* ew  = (const float*)d_in[3];
    const float* W1  = (const float*)d_in[4];
    const float* b1  = (const float*)d_in[5];
    const float* W2  = (const float*)d_in[6];
    const float* b2  = (const float*)d_in[7];
    float* out = (float*)d_out;

    float *agg1, *h2;
    cudaGetSymbolAddress((void**)&agg1, g_agg1);
    cudaGetSymbolAddress((void**)&h2,   g_h2);

    const int M = N_NODES;

    // --- dst-sort build (g_count zeroed by previous call's scatter) ---
    hist_kernel<<<(N_EDGES + 255) / 256, 256>>>(ed);
    blocksum_kernel<<<N_BLK, 256>>>();
    offsets_kernel<<<N_BLK, 256>>>();
    scatter_kernel<<<(N_EDGES + 255) / 256, 256>>>(es, ed, ew);

    // 1) h1 = x @ W1  (tf32 HMMA, fp16 output, preload pipeline)
    gemm1_mma_kernel<<<(M + 127) / 128, 256>>>(x, W1, M);

    // 2) agg1 = b1; += chunked segmented scatter-reduce (fp16 gathers)
    {
        size_t total = (size_t)M * NHID;
        init_bias128_kernel<<<(unsigned)((total + 255) / 256), 256>>>(agg1, b1);
    }
    spmm1_seg_kernel<<<(N_CHUNK + 7) / 8, 256>>>();

    // 3) h2 = relu(agg1) @ W2  (tf32 HMMA)
    gemm2_mma_kernel<<<(M + 127) / 128, 256>>>(agg1, W2, h2, M);

    // 4) out = b2; += chunked segmented scatter-reduce
    {
        size_t total = (size_t)M * NCLASS;
        init_bias40_kernel<<<(unsigned)((total + 255) / 256), 256>>>(out, b2);
    }
    {
        size_t threads = (size_t)N_CHUNK * 10;
        spmm2_seg_kernel<<<(unsigned)((threads + 255) / 256), 256>>>(out);
    }
}

// round 15
// speedup vs baseline: 1.1235x; 1.1235x over previous
#include <cuda_runtime.h>
#include <cuda_bf16.h>
#include <cuda_fp16.h>
#include <cstdint>

// Problem constants (fixed by the reference)
#define N_NODES 50000
#define N_EDGES 800000
#define NFEAT   512
#define NHID    128
#define NCLASS  40

#define EC      16                 // edges per chunk (800000 % 16 == 0)
#define N_CHUNK (N_EDGES / EC)     // 50000

// Device scratch (no cudaMalloc allowed)
__device__ __half g_h1h[N_NODES * NHID];  // support1 = x @ W1 (fp16, 12.8 MB)
__device__ float g_agg1[N_NODES * NHID];  // aggregated layer-1 out
__device__ float g_h2[N_NODES * NCLASS];  // support2 = relu(h) @ W2

// sort scratch (g_count zero at load; scatter re-zeroes it for next call)
__device__ int   g_count[N_NODES];
__device__ int   g_rank[N_EDGES];
__device__ int   g_off[N_NODES];
#define N_BLK ((N_NODES + 255) / 256)     // 196
__device__ int   g_bsum[N_BLK];
__device__ uint2 g_edge8[N_EDGES];        // (src | dst<<16, w_bits), dst-sorted

__device__ __forceinline__ uint32_t cvt_tf32(float f) {
    uint32_t out;
    asm("cvt.rna.tf32.f32 %0, %1;" : "=r"(out) : "f"(f));
    return out;
}

__device__ __forceinline__ void mma_tf32(
    float& d0, float& d1, float& d2, float& d3,
    uint32_t a0, uint32_t a1, uint32_t a2, uint32_t a3,
    uint32_t b0, uint32_t b1)
{
    asm volatile(
        "mma.sync.aligned.m16n8k8.row.col.f32.tf32.tf32.f32 "
        "{%0,%1,%2,%3}, {%4,%5,%6,%7}, {%8,%9}, {%0,%1,%2,%3};"
        : "+f"(d0), "+f"(d1), "+f"(d2), "+f"(d3)
        : "r"(a0), "r"(a1), "r"(a2), "r"(a3), "r"(b0), "r"(b1));
}

__device__ __forceinline__ void red_add_v4(float* addr, float4 v)
{
    asm volatile("red.global.add.v4.f32 [%0], {%1, %2, %3, %4};"
                 :: "l"(addr), "f"(v.x), "f"(v.y), "f"(v.z), "f"(v.w)
                 : "memory");
}

// ===========================================================================
// GEMM1 (HMMA tf32): h1h[M,128] = tf32(A[M,512]) @ tf32(W1[512,128]) -> fp16
// CTA tile 128x128, BK=32, 8 warps, warp tile 32(M) x 64(N), frag-permuted smem
// (identical to the 231.6us R12 version)
// ===========================================================================
#define G1_BK 32

__global__ __launch_bounds__(256) void gemm1_mma_kernel(
    const float* __restrict__ A, const float* __restrict__ W1, int M)
{
    __shared__ uint32_t sA[4 * 8 * 32 * 4];   // 16 KB
    __shared__ uint32_t sB[4 * 8 * 32 * 4];   // 16 KB

    const int tid  = threadIdx.x;
    const int lane = tid & 31;
    const int wid  = tid >> 5;
    const int warp_m = wid & 3;
    const int warp_n = wid >> 2;
    const int m0 = blockIdx.x * 128;

    float acc[2][8][4];
#pragma unroll
    for (int mi = 0; mi < 2; mi++)
#pragma unroll
        for (int nt = 0; nt < 8; nt++)
#pragma unroll
            for (int j = 0; j < 4; j++) acc[mi][nt][j] = 0.0f;

    for (int k0 = 0; k0 < NFEAT; k0 += G1_BK) {
#pragma unroll
        for (int t = 0; t < 4; t++) {
            int i = tid + t * 256;
            int r = i >> 3;
            int q = i & 7;
            float4 v = make_float4(0.f, 0.f, 0.f, 0.f);
            if (m0 + r < M)
                v = *(const float4*)&A[(size_t)(m0 + r) * NFEAT + k0 + q * 4];
            uint32_t u[4] = {cvt_tf32(v.x), cvt_tf32(v.y), cvt_tf32(v.z), cvt_tf32(v.w)};
            int ks   = q >> 1;
            int mt   = r >> 4;
            int slot = ((r >> 3) & 1) + 2 * (q & 1);
            int base = ((ks * 8 + mt) * 32 + (r & 7) * 4) * 4 + slot;
#pragma unroll
            for (int j = 0; j < 4; j++) sA[base + j * 4] = u[j];
        }
#pragma unroll
        for (int t = 0; t < 4; t++) {
            int i = tid + t * 256;
            int kk = i >> 5;
            int nf = i & 31;
            float4 v = *(const float4*)&W1[(size_t)(k0 + kk) * NHID + nf * 4];
            uint32_t u[4] = {cvt_tf32(v.x), cvt_tf32(v.y), cvt_tf32(v.z), cvt_tf32(v.w)};
            int ks   = kk >> 3;
            int kc   = kk & 7;
            int ntp  = nf >> 2;
            int slot = ((nf >> 1) & 1) * 2 + (kc >> 2);
            int base = ((ks * 8 + ntp) * 32 + (nf & 1) * 16 + (kc & 3)) * 4 + slot;
#pragma unroll
            for (int j = 0; j < 4; j++) sB[base + j * 16] = u[j];
        }
        __syncthreads();

#pragma unroll
        for (int ks = 0; ks < 4; ks++) {
            uint4 af[2];
#pragma unroll
            for (int mi = 0; mi < 2; mi++) {
                int mt = warp_m * 2 + mi;
                af[mi] = *(const uint4*)&sA[((ks * 8 + mt) * 32 + lane) * 4];
            }
#pragma unroll
            for (int np = 0; np < 4; np++) {
                int ntp = warp_n * 4 + np;
                uint4 bf = *(const uint4*)&sB[((ks * 8 + ntp) * 32 + lane) * 4];
#pragma unroll
                for (int mi = 0; mi < 2; mi++) {
                    mma_tf32(acc[mi][np*2][0], acc[mi][np*2][1],
                             acc[mi][np*2][2], acc[mi][np*2][3],
                             af[mi].x, af[mi].y, af[mi].z, af[mi].w,
                             bf.x, bf.y);
                    mma_tf32(acc[mi][np*2+1][0], acc[mi][np*2+1][1],
                             acc[mi][np*2+1][2], acc[mi][np*2+1][3],
                             af[mi].x, af[mi].y, af[mi].z, af[mi].w,
                             bf.z, bf.w);
                }
            }
        }
        __syncthreads();
    }

    // epilogue -> fp16 h1
#pragma unroll
    for (int mi = 0; mi < 2; mi++) {
        int r_base = m0 + warp_m * 32 + mi * 16 + (lane >> 2);
#pragma unroll
        for (int nt = 0; nt < 8; nt++) {
            int col = warp_n * 64 + nt * 8 + (lane & 3) * 2;
            if (r_base < M)
                *(__half2*)&g_h1h[(size_t)r_base * NHID + col] =
                    __floats2half2_rn(acc[mi][nt][0], acc[mi][nt][1]);
            if (r_base + 8 < M)
                *(__half2*)&g_h1h[(size_t)(r_base + 8) * NHID + col] =
                    __floats2half2_rn(acc[mi][nt][2], acc[mi][nt][3]);
        }
    }
}

// ===========================================================================
// Sort build: hist(+rank) -> blocksum -> offsets -> scatter(+inits+zero)
// ===========================================================================
__global__ void hist_kernel(const int* __restrict__ edst)
{
    int e = blockIdx.x * blockDim.x + threadIdx.x;
    if (e < N_EDGES) g_rank[e] = atomicAdd(&g_count[edst[e]], 1);
}

__global__ __launch_bounds__(256) void blocksum_kernel()
{
    __shared__ int ws[8];
    int i = blockIdx.x * 256 + threadIdx.x;
    int c = (i < N_NODES) ? g_count[i] : 0;
    int lane = threadIdx.x & 31, w = threadIdx.x >> 5;
    int v = c;
#pragma unroll
    for (int o = 16; o > 0; o >>= 1) v += __shfl_down_sync(0xFFFFFFFFu, v, o);
    if (lane == 0) ws[w] = v;
    __syncthreads();
    if (threadIdx.x == 0) {
        int s = 0;
#pragma unroll
        for (int j = 0; j < 8; j++) s += ws[j];
        g_bsum[blockIdx.x] = s;
    }
}

// every block redundantly scans the 196 block sums, then scans its 256 counts
__global__ __launch_bounds__(256) void offsets_kernel()
{
    __shared__ int sb[256];
    __shared__ int sm[256];
    const int tid = threadIdx.x;

    int bsv = (tid < N_BLK) ? g_bsum[tid] : 0;
    sb[tid] = bsv;
    __syncthreads();
#pragma unroll
    for (int o = 1; o < 256; o <<= 1) {
        int n = (tid >= o) ? sb[tid - o] : 0;
        __syncthreads();
        sb[tid] += n;
        __syncthreads();
    }
    int blk_excl = sb[blockIdx.x] - g_bsum[blockIdx.x];

    int i = blockIdx.x * 256 + tid;
    int c = (i < N_NODES) ? g_count[i] : 0;
    sm[tid] = c;
    __syncthreads();
#pragma unroll
    for (int o = 1; o < 256; o <<= 1) {
        int n = (tid >= o) ? sm[tid - o] : 0;
        __syncthreads();
        sm[tid] += n;
        __syncthreads();
    }
    if (i < N_NODES) g_off[i] = blk_excl + sm[tid] - c;
}

// scatter + bias-inits + g_count re-zero (scatter is issue-starved; the extra
// streaming writes ride in the idle issue slots)
__global__ __launch_bounds__(256) void scatter_kernel(
    const int* __restrict__ esrc, const int* __restrict__ edst,
    const float* __restrict__ ew,
    const float* __restrict__ b1, const float* __restrict__ b2,
    float* __restrict__ out)
{
    __shared__ float sb1[NHID];
    __shared__ float sb2[NCLASS];
    if (threadIdx.x < NHID) sb1[threadIdx.x] = b1[threadIdx.x];
    if (threadIdx.x < NCLASS) sb2[threadIdx.x] = b2[threadIdx.x];
    __syncthreads();

    const unsigned e = blockIdx.x * 256 + threadIdx.x;   // 0 .. 800255
    if (e < N_EDGES) {
        int d = edst[e];
        int pos = g_off[d] + g_rank[e];
        g_edge8[pos] = make_uint2((unsigned)esrc[e] | ((unsigned)d << 16),
                                  (unsigned)__float_as_int(ew[e]));
    }
    if (e < N_NODES) g_count[e] = 0;   // ready for next call

    // agg1 = broadcast b1  (6.4M floats, 8 per thread)
    const unsigned NT = 800256u;       // 3126 blocks * 256
    for (size_t i = e; i < (size_t)N_NODES * NHID; i += NT)
        g_agg1[i] = sb1[i & (NHID - 1)];
    // out = broadcast b2   (2M floats, ~2.5 per thread)
    for (size_t i = e; i < (size_t)N_NODES * NCLASS; i += NT)
        out[i] = sb2[i % NCLASS];
}

// ===========================================================================
// SpMM layer 1: warp per 16-edge chunk of dst-sorted edges, fp16 gathers.
// Register accumulation across equal-dst runs; RED only at run boundaries.
// (R12 simple-loop version, 8B edge records)
// ===========================================================================
__global__ __launch_bounds__(256) void spmm1_seg_kernel()
{
    const int wid  = threadIdx.x >> 5;
    const int lane = threadIdx.x & 31;
    const int chunk = blockIdx.x * 8 + wid;
    if (chunk >= N_CHUNK) return;
    const int base = chunk * EC;

    float4 acc = make_float4(0.f, 0.f, 0.f, 0.f);
    unsigned cur_d = g_edge8[base].x >> 16;

#pragma unroll
    for (int i = 0; i < EC; i++) {
        uint2 ed = g_edge8[base + i];
        unsigned src = ed.x & 0xFFFFu;
        unsigned dst = ed.x >> 16;
        uint2 raw = *(const uint2*)&g_h1h[(size_t)src * NHID + lane * 4];
        float w = __int_as_float((int)ed.y);
        if (dst != cur_d) {     // warp-uniform branch
            red_add_v4(&g_agg1[(size_t)cur_d * NHID + lane * 4], acc);
            acc = make_float4(0.f, 0.f, 0.f, 0.f);
            cur_d = dst;
        }
        float2 f0 = __half22float2(*(__half2*)&raw.x);
        float2 f1 = __half22float2(*(__half2*)&raw.y);
        acc.x += w * f0.x; acc.y += w * f0.y;
        acc.z += w * f1.x; acc.w += w * f1.y;
    }
    red_add_v4(&g_agg1[(size_t)cur_d * NHID + lane * 4], acc);
}

// ===========================================================================
// GEMM2 (HMMA tf32): C[M,40] = tf32(relu(H[M,128])) @ tf32(W2[128,40])
// ===========================================================================
__global__ __launch_bounds__(256) void gemm2_mma_kernel(
    const float* __restrict__ H, const float* __restrict__ W2,
    float* __restrict__ C, int M)
{
    __shared__ uint32_t sH[4 * 8 * 32 * 4];    // 16 KB
    __shared__ uint32_t sW2[16 * 3 * 32 * 4];  // 24 KB

    const int tid  = threadIdx.x;
    const int lane = tid & 31;
    const int wid  = tid >> 5;
    const int m0 = blockIdx.x * 128;

    for (int i = tid; i < 1280; i += 256) {
        int kk = i / 10;
        int nf = i % 10;
        float4 v = *(const float4*)&W2[(size_t)kk * NCLASS + nf * 4];
        uint32_t u[4] = {cvt_tf32(v.x), cvt_tf32(v.y), cvt_tf32(v.z), cvt_tf32(v.w)};
        int gks  = kk >> 3;
        int kc   = kk & 7;
        int ntp  = nf >> 2;
        int slot = ((nf >> 1) & 1) * 2 + (kc >> 2);
        int base = ((gks * 3 + ntp) * 32 + (nf & 1) * 16 + (kc & 3)) * 4 + slot;
#pragma unroll
        for (int j = 0; j < 4; j++) sW2[base + j * 16] = u[j];
    }

    float acc[5][4];
#pragma unroll
    for (int nt = 0; nt < 5; nt++)
#pragma unroll
        for (int j = 0; j < 4; j++) acc[nt][j] = 0.0f;

    for (int kc4 = 0; kc4 < 4; kc4++) {
        __syncthreads();
#pragma unroll
        for (int t = 0; t < 4; t++) {
            int i = tid + t * 256;
            int r = i >> 3;
            int q = i & 7;
            float4 v = make_float4(0.f, 0.f, 0.f, 0.f);
            if (m0 + r < M) {
                v = *(const float4*)&H[(size_t)(m0 + r) * NHID + kc4 * 32 + q * 4];
                v.x = fmaxf(v.x, 0.f); v.y = fmaxf(v.y, 0.f);
                v.z = fmaxf(v.z, 0.f); v.w = fmaxf(v.w, 0.f);
            }
            uint32_t u[4] = {cvt_tf32(v.x), cvt_tf32(v.y), cvt_tf32(v.z), cvt_tf32(v.w)};
            int ks   = q >> 1;
            int mt   = r >> 4;
            int slot = ((r >> 3) & 1) + 2 * (q & 1);
            int base = ((ks * 8 + mt) * 32 + (r & 7) * 4) * 4 + slot;
#pragma unroll
            for (int j = 0; j < 4; j++) sH[base + j * 4] = u[j];
        }
        __syncthreads();

#pragma unroll
        for (int ks = 0; ks < 4; ks++) {
            int gks = kc4 * 4 + ks;
            uint4 af = *(const uint4*)&sH[((ks * 8 + wid) * 32 + lane) * 4];
            uint4 b0 = *(const uint4*)&sW2[((gks * 3 + 0) * 32 + lane) * 4];
            uint4 b1 = *(const uint4*)&sW2[((gks * 3 + 1) * 32 + lane) * 4];
            uint4 b2 = *(const uint4*)&sW2[((gks * 3 + 2) * 32 + lane) * 4];
            mma_tf32(acc[0][0], acc[0][1], acc[0][2], acc[0][3],
                     af.x, af.y, af.z, af.w, b0.x, b0.y);
            mma_tf32(acc[1][0], acc[1][1], acc[1][2], acc[1][3],
                     af.x, af.y, af.z, af.w, b0.z, b0.w);
            mma_tf32(acc[2][0], acc[2][1], acc[2][2], acc[2][3],
                     af.x, af.y, af.z, af.w, b1.x, b1.y);
            mma_tf32(acc[3][0], acc[3][1], acc[3][2], acc[3][3],
                     af.x, af.y, af.z, af.w, b1.z, b1.w);
            mma_tf32(acc[4][0], acc[4][1], acc[4][2], acc[4][3],
                     af.x, af.y, af.z, af.w, b2.x, b2.y);
        }
    }

    int r = m0 + wid * 16 + (lane >> 2);
#pragma unroll
    for (int nt = 0; nt < 5; nt++) {
        int col = nt * 8 + (lane & 3) * 2;
        if (r < M)
            *(float2*)&C[(size_t)r * NCLASS + col] =
                make_float2(acc[nt][0], acc[nt][1]);
        if (r + 8 < M)
            *(float2*)&C[(size_t)(r + 8) * NCLASS + col] =
                make_float2(acc[nt][2], acc[nt][3]);
    }
}

// ===========================================================================
// SpMM layer 2: thread = (16-edge chunk, float4-chunk c of 10), simple loop
// ===========================================================================
__global__ __launch_bounds__(256) void spmm2_seg_kernel(float* __restrict__ out)
{
    unsigned gid = blockIdx.x * blockDim.x + threadIdx.x;
    unsigned chunk = gid / 10;
    unsigned c = gid % 10;
    if (chunk >= N_CHUNK) return;
    const int base = chunk * EC;

    float4 acc = make_float4(0.f, 0.f, 0.f, 0.f);
    unsigned cur_d = g_edge8[base].x >> 16;

#pragma unroll
    for (int i = 0; i < EC; i++) {
        uint2 ed = g_edge8[base + i];
        unsigned src = ed.x & 0xFFFFu;
        unsigned dst = ed.x >> 16;
        float4 v = *(const float4*)&g_h2[(size_t)src * NCLASS + c * 4];
        float w = __int_as_float((int)ed.y);
        if (dst != cur_d) {
            red_add_v4(&out[(size_t)cur_d * NCLASS + c * 4], acc);
            acc = make_float4(0.f, 0.f, 0.f, 0.f);
            cur_d = dst;
        }
        acc.x += w * v.x; acc.y += w * v.y;
        acc.z += w * v.z; acc.w += w * v.w;
    }
    red_add_v4(&out[(size_t)cur_d * NCLASS + c * 4], acc);
}

// ---------------------------------------------------------------------------
// kernel_launch
// inputs: 0=x 1=edge_src 2=edge_dst 3=edge_weight 4=W1 5=b1 6=W2 7=b2
// ---------------------------------------------------------------------------
extern "C" void kernel_launch(void* const* d_in, const int* in_sizes, int n_in,
                              void* d_out, int out_size)
{
    const float* x   = (const float*)d_in[0];
    const int*   es  = (const int*)d_in[1];
    const int*   ed  = (const int*)d_in[2];
    const float* ew  = (const float*)d_in[3];
    const float* W1  = (const float*)d_in[4];
    const float* b1  = (const float*)d_in[5];
    const float* W2  = (const float*)d_in[6];
    const float* b2  = (const float*)d_in[7];
    float* out = (float*)d_out;

    float *agg1, *h2;
    cudaGetSymbolAddress((void**)&agg1, g_agg1);
    cudaGetSymbolAddress((void**)&h2,   g_h2);

    const int M = N_NODES;

    // --- dst-sort build (g_count zeroed by previous call's scatter) ---
    hist_kernel<<<(N_EDGES + 255) / 256, 256>>>(ed);
    blocksum_kernel<<<N_BLK, 256>>>();
    offsets_kernel<<<N_BLK, 256>>>();
    scatter_kernel<<<3126, 256>>>(es, ed, ew, b1, b2, out);

    // 1) h1 = x @ W1  (tf32 HMMA, fp16 output)
    gemm1_mma_kernel<<<(M + 127) / 128, 256>>>(x, W1, M);

    // 2) agg1 (pre-seeded with b1) += chunked segmented scatter-reduce
    spmm1_seg_kernel<<<(N_CHUNK + 7) / 8, 256>>>();

    // 3) h2 = relu(agg1) @ W2  (tf32 HMMA)
    gemm2_mma_kernel<<<(M + 127) / 128, 256>>>(agg1, W2, h2, M);

    // 4) out (pre-seeded with b2) += chunked segmented scatter-reduce
    {
        size_t threads = (size_t)N_CHUNK * 10;
        spmm2_seg_kernel<<<(unsigned)((threads + 255) / 256), 256>>>(out);
    }
}